// round 1
// baseline (speedup 1.0000x reference)
#include <cuda_runtime.h>
#include <math.h>

#define BB 32
#define NN 512
#define HH 128

// scratch for intermediate h (B*N*H fp32 = 8MB) — __device__ global, no allocation
__device__ float g_h[BB * NN * HH];

// ---------------------------------------------------------------------------
// K1: h[b,n,k] = silu(layernorm(sum_h s[b,n,h]*W1[k,h] + b1[k]))
// grid: 512 blocks (32 rows each), 256 threads. Dynamic smem:
//   W1T[128][132]  (transposed, padded: conflict-free float4 reads)
//   sT [128][33]   (transposed, padded; reused as hp[32][128] for LN stage)
// ---------------------------------------------------------------------------
__global__ void k1_lin_ln_silu(const float* __restrict__ s,
                               const float* __restrict__ W1,
                               const float* __restrict__ b1) {
    extern __shared__ float smem[];
    float* W1T = smem;                 // 128*132 floats
    float* sT  = smem + 128 * 132;     // 128*33 floats (>= 32*128 for reuse)

    const int t    = threadIdx.x;
    const int row0 = blockIdx.x * 32;

    // Load W1 transposed: W1T[h*132 + c] = W1[c*128 + h]
#pragma unroll 8
    for (int k = 0; k < 64; ++k) {
        int u = t + k * 256;           // 0..16383
        int c = u >> 7, h = u & 127;
        W1T[h * 132 + c] = W1[u];
    }
    // Load s tile transposed: sT[h*33 + r] = s[(row0+r)*128 + h]
#pragma unroll 8
    for (int k = 0; k < 16; ++k) {
        int u = t + k * 256;           // 0..4095
        int r = u >> 7, h = u & 127;
        sT[h * 33 + r] = s[row0 * 128 + u];
    }
    __syncthreads();

    const int cg = t & 31;   // column group: cols 4*cg..4*cg+3
    const int rg = t >> 5;   // row group (== warp id): rows 4*rg..4*rg+3

    float4 acc0 = make_float4(0.f, 0.f, 0.f, 0.f);
    float4 acc1 = acc0, acc2 = acc0, acc3 = acc0;

    const float4* W1T4 = (const float4*)W1T;   // row stride 33 float4
#pragma unroll 4
    for (int h = 0; h < 128; ++h) {
        float4 w = W1T4[h * 33 + cg];          // conflict-free across lanes
        float a0 = sT[h * 33 + rg * 4 + 0];    // broadcast (warp-uniform)
        float a1 = sT[h * 33 + rg * 4 + 1];
        float a2 = sT[h * 33 + rg * 4 + 2];
        float a3 = sT[h * 33 + rg * 4 + 3];
        acc0.x += a0 * w.x; acc0.y += a0 * w.y; acc0.z += a0 * w.z; acc0.w += a0 * w.w;
        acc1.x += a1 * w.x; acc1.y += a1 * w.y; acc1.z += a1 * w.z; acc1.w += a1 * w.w;
        acc2.x += a2 * w.x; acc2.y += a2 * w.y; acc2.z += a2 * w.z; acc2.w += a2 * w.w;
        acc3.x += a3 * w.x; acc3.y += a3 * w.y; acc3.z += a3 * w.z; acc3.w += a3 * w.w;
    }
    {   // + b1
        float4 bv = ((const float4*)b1)[cg];
        acc0.x += bv.x; acc0.y += bv.y; acc0.z += bv.z; acc0.w += bv.w;
        acc1.x += bv.x; acc1.y += bv.y; acc1.z += bv.z; acc1.w += bv.w;
        acc2.x += bv.x; acc2.y += bv.y; acc2.z += bv.z; acc2.w += bv.w;
        acc3.x += bv.x; acc3.y += bv.y; acc3.z += bv.z; acc3.w += bv.w;
    }

    // stage pre-LN values into hp[32][128] (reuse sT region)
    __syncthreads();                 // everyone done reading sT
    float4* hp4 = (float4*)sT;       // [32][32] float4, row stride 32
    hp4[(rg * 4 + 0) * 32 + cg] = acc0;
    hp4[(rg * 4 + 1) * 32 + cg] = acc1;
    hp4[(rg * 4 + 2) * 32 + cg] = acc2;
    hp4[(rg * 4 + 3) * 32 + cg] = acc3;
    __syncthreads();

    // LayerNorm + SiLU: warp rg handles rows 4*rg..4*rg+3, lane cg holds 4 elems
    const float inv128 = 1.0f / 128.0f;
#pragma unroll
    for (int rr = 0; rr < 4; ++rr) {
        int row = rg * 4 + rr;
        float4 x = hp4[row * 32 + cg];
        float sm = x.x + x.y + x.z + x.w;
        float sq = x.x * x.x + x.y * x.y + x.z * x.z + x.w * x.w;
#pragma unroll
        for (int o = 16; o > 0; o >>= 1) {
            sm += __shfl_xor_sync(0xFFFFFFFFu, sm, o);
            sq += __shfl_xor_sync(0xFFFFFFFFu, sq, o);
        }
        float mu  = sm * inv128;
        float var = sq * inv128 - mu * mu;
        float rs  = rsqrtf(var + 1e-5f);
        float4 y;
        y.x = (x.x - mu) * rs; y.y = (x.y - mu) * rs;
        y.z = (x.z - mu) * rs; y.w = (x.w - mu) * rs;
        // silu
        y.x = y.x / (1.0f + __expf(-y.x));
        y.y = y.y / (1.0f + __expf(-y.y));
        y.z = y.z / (1.0f + __expf(-y.z));
        y.w = y.w / (1.0f + __expf(-y.w));
        ((float4*)g_h)[((row0 + row) * 128) / 4 + cg] = y;
    }
}

// ---------------------------------------------------------------------------
// K2: v[b,i,c,d] = sum_j mask[b,i,j] * ev[b,i,j,c] * h[b,j,d]
// grid: 32 batches * 16 i-tiles = 512 blocks, 256 threads.
// Warp wi owns i in [wi*4, wi*4+4); lane owns d in [4*lane, 4*lane+4).
// mask is warp-uniform -> divergence-free skip of zero rows (~50% FFMA saved).
// ---------------------------------------------------------------------------
__global__ void __launch_bounds__(256)
k2_cfconv(const float* __restrict__ ev,
          const float* __restrict__ mask,
          float* __restrict__ out) {
    __shared__ float h_s[32 * 128];     // h rows j0..j0+31
    __shared__ float ev_s[32 * 96];     // ev_s[i][j*3+c], i local
    __shared__ float mk_s[32 * 32];     // mk_s[i][j]

    const int t    = threadIdx.x;
    const int b    = blockIdx.x >> 4;
    const int i0   = (blockIdx.x & 15) * 32;
    const int lane = t & 31;
    const int wi   = t >> 5;

    float4 acc[4][3];
#pragma unroll
    for (int ii = 0; ii < 4; ++ii)
#pragma unroll
        for (int c = 0; c < 3; ++c)
            acc[ii][c] = make_float4(0.f, 0.f, 0.f, 0.f);

    const float4* hb4 = (const float4*)(g_h + b * NN * HH);
    float4* hs4 = (float4*)h_s;
    float4* es4 = (float4*)ev_s;
    float4* mk4 = (float4*)mk_s;

    for (int j0 = 0; j0 < NN; j0 += 32) {
        __syncthreads();
        // h tile: 32 rows x 128 = 1024 float4
#pragma unroll
        for (int k = 0; k < 4; ++k)
            hs4[t + k * 256] = hb4[j0 * 32 + t + k * 256];
        // ev tile: 32 i * 96 floats = 768 float4; u = i*24 + q
#pragma unroll
        for (int k = 0; k < 3; ++k) {
            int u = t + k * 256;
            int i = u / 24, q = u - i * 24;
            es4[u] = ((const float4*)ev)[(((b * 512 + i0 + i) * 512 + j0) * 3) / 4 + q];
        }
        // mask tile: 32 i * 32 = 256 float4; t = i*8 + q
        {
            int i = t >> 3, q = t & 7;
            mk4[t] = ((const float4*)mask)[((b * 512 + i0 + i) * 512 + j0) / 4 + q];
        }
        __syncthreads();

        for (int j = 0; j < 32; ++j) {
            float4 hv = hs4[j * 32 + lane];
#pragma unroll
            for (int ii = 0; ii < 4; ++ii) {
                int i = wi * 4 + ii;
                float mv = mk_s[i * 32 + j];     // warp-uniform
                if (mv != 0.0f) {                // mask is exactly 0 or 1
#pragma unroll
                    for (int c = 0; c < 3; ++c) {
                        float e = ev_s[i * 96 + j * 3 + c];
                        acc[ii][c].x += e * hv.x;
                        acc[ii][c].y += e * hv.y;
                        acc[ii][c].z += e * hv.z;
                        acc[ii][c].w += e * hv.w;
                    }
                }
            }
        }
    }

#pragma unroll
    for (int ii = 0; ii < 4; ++ii) {
        int i = i0 + wi * 4 + ii;
#pragma unroll
        for (int c = 0; c < 3; ++c)
            ((float4*)out)[((b * 512 + i) * 3 + c) * 32 + lane] = acc[ii][c];
    }
}

// ---------------------------------------------------------------------------
extern "C" void kernel_launch(void* const* d_in, const int* in_sizes, int n_in,
                              void* d_out, int out_size) {
    const float* s    = (const float*)d_in[0];   // (32,512,128)
    const float* ev   = (const float*)d_in[1];   // (32,512,512,3)
    const float* mask = (const float*)d_in[2];   // (32,512,512,1)
    const float* W1   = (const float*)d_in[3];   // (128,128)
    const float* b1   = (const float*)d_in[4];   // (128,)
    float* out = (float*)d_out;                  // (32,512,3,128)

    const int k1_smem = (128 * 132 + 128 * 33) * (int)sizeof(float);  // 84480 B
    cudaFuncSetAttribute(k1_lin_ln_silu,
                         cudaFuncAttributeMaxDynamicSharedMemorySize, k1_smem);

    k1_lin_ln_silu<<<(BB * NN) / 32, 256, k1_smem>>>(s, W1, b1);
    k2_cfconv<<<BB * (NN / 32), 256>>>(ev, mask, out);
}

// round 3
// speedup vs baseline: 1.9150x; 1.9150x over previous
#include <cuda_runtime.h>
#include <cuda_bf16.h>
#include <math.h>
#include <stdint.h>

#define BB 32
#define NN 512
#define HH 128

// hT[b][d][j], each uint32 = bf16 hi (low half) | bf16 lo (high half). 8 MB.
__device__ uint32_t g_hT[BB * HH * NN];

__device__ __forceinline__ uint32_t smem_u32(const void* p) {
    uint32_t a;
    asm("{ .reg .u64 t; cvta.to.shared.u64 t, %1; cvt.u32.u64 %0, t; }"
        : "=r"(a) : "l"(p));
    return a;
}

// ---------------------------------------------------------------------------
// K1: h = silu(LN(s @ W1^T + b1)); writes transposed split-bf16 packed hT.
// ---------------------------------------------------------------------------
__global__ void __launch_bounds__(256)
k1_lin_ln_silu(const float* __restrict__ s,
               const float* __restrict__ W1,
               const float* __restrict__ b1) {
    extern __shared__ float smem[];
    float*    W1T = smem;                           // 128*132 floats
    float*    sT  = smem + 128 * 132;               // 128*33 floats (reused as hp)
    uint32_t* tr  = (uint32_t*)(smem + 128 * 132 + 128 * 33);  // 128*33 u32

    const int t    = threadIdx.x;
    const int row0 = blockIdx.x * 32;

#pragma unroll 8
    for (int k = 0; k < 64; ++k) {
        int u = t + k * 256;
        int c = u >> 7, h = u & 127;
        W1T[h * 132 + c] = W1[u];
    }
#pragma unroll 8
    for (int k = 0; k < 16; ++k) {
        int u = t + k * 256;
        int r = u >> 7, h = u & 127;
        sT[h * 33 + r] = s[row0 * 128 + u];
    }
    __syncthreads();

    const int cg = t & 31;
    const int rg = t >> 5;

    float4 acc0 = make_float4(0.f, 0.f, 0.f, 0.f);
    float4 acc1 = acc0, acc2 = acc0, acc3 = acc0;

    const float4* W1T4 = (const float4*)W1T;
#pragma unroll 4
    for (int h = 0; h < 128; ++h) {
        float4 w = W1T4[h * 33 + cg];
        float a0 = sT[h * 33 + rg * 4 + 0];
        float a1 = sT[h * 33 + rg * 4 + 1];
        float a2 = sT[h * 33 + rg * 4 + 2];
        float a3 = sT[h * 33 + rg * 4 + 3];
        acc0.x += a0 * w.x; acc0.y += a0 * w.y; acc0.z += a0 * w.z; acc0.w += a0 * w.w;
        acc1.x += a1 * w.x; acc1.y += a1 * w.y; acc1.z += a1 * w.z; acc1.w += a1 * w.w;
        acc2.x += a2 * w.x; acc2.y += a2 * w.y; acc2.z += a2 * w.z; acc2.w += a2 * w.w;
        acc3.x += a3 * w.x; acc3.y += a3 * w.y; acc3.z += a3 * w.z; acc3.w += a3 * w.w;
    }
    {
        float4 bv = ((const float4*)b1)[cg];
        acc0.x += bv.x; acc0.y += bv.y; acc0.z += bv.z; acc0.w += bv.w;
        acc1.x += bv.x; acc1.y += bv.y; acc1.z += bv.z; acc1.w += bv.w;
        acc2.x += bv.x; acc2.y += bv.y; acc2.z += bv.z; acc2.w += bv.w;
        acc3.x += bv.x; acc3.y += bv.y; acc3.z += bv.z; acc3.w += bv.w;
    }

    __syncthreads();
    float4* hp4 = (float4*)sT;    // [32 rows][32 float4]
    hp4[(rg * 4 + 0) * 32 + cg] = acc0;
    hp4[(rg * 4 + 1) * 32 + cg] = acc1;
    hp4[(rg * 4 + 2) * 32 + cg] = acc2;
    hp4[(rg * 4 + 3) * 32 + cg] = acc3;
    __syncthreads();

    const float inv128 = 1.0f / 128.0f;
#pragma unroll
    for (int rr = 0; rr < 4; ++rr) {
        int row = rg * 4 + rr;
        float4 x = hp4[row * 32 + cg];
        float sm = x.x + x.y + x.z + x.w;
        float sq = x.x * x.x + x.y * x.y + x.z * x.z + x.w * x.w;
#pragma unroll
        for (int o = 16; o > 0; o >>= 1) {
            sm += __shfl_xor_sync(0xFFFFFFFFu, sm, o);
            sq += __shfl_xor_sync(0xFFFFFFFFu, sq, o);
        }
        float mu  = sm * inv128;
        float var = sq * inv128 - mu * mu;
        float rs  = rsqrtf(var + 1e-5f);
        float y[4];
        y[0] = (x.x - mu) * rs; y[1] = (x.y - mu) * rs;
        y[2] = (x.z - mu) * rs; y[3] = (x.w - mu) * rs;
#pragma unroll
        for (int q = 0; q < 4; ++q) {
            float yv = y[q] / (1.0f + __expf(-y[q]));    // silu
            __nv_bfloat16 hi = __float2bfloat16(yv);
            __nv_bfloat16 lo = __float2bfloat16(yv - __bfloat162float(hi));
            uint32_t pk = (uint32_t)__bfloat16_as_ushort(hi)
                        | ((uint32_t)__bfloat16_as_ushort(lo) << 16);
            tr[(4 * cg + q) * 33 + row] = pk;
        }
    }
    __syncthreads();

    const int b  = row0 >> 9;
    const int n0 = row0 & 511;
#pragma unroll
    for (int k = 0; k < 16; ++k) {
        int u = t + k * 256;          // 0..4095
        int d = u >> 5, n = u & 31;
        g_hT[(b * 128 + d) * 512 + n0 + n] = tr[d * 33 + n];
    }
}

// ---------------------------------------------------------------------------
// K2: mma.sync (HMMA bf16, fp32 accum) split-bf16 CFConv.
// grid: 32 b x 8 i-tiles (64 i each) = 256 CTAs, 512 threads (16 warps, 4m x 4n).
// Warp tile: m16 (i) x n32 (d) x 3 c. K-chunk = 64 j, 4 k16-steps, 3 passes.
// smem layout (bytes):
//   A[c][split][i(64)][row 144B]   c-stride 18432, split-stride 9216
//   B[split][d(128)][row 144B]    at 55296, split-stride 18432
//   mk[i(64)][68 floats]          at 92160, row 272B
// total 109568
// ---------------------------------------------------------------------------
#define A_C_STRIDE   18432
#define A_S_STRIDE   9216
#define SM_ROW       144
#define B_BASE       55296
#define B_S_STRIDE   18432
#define MK_BASE      92160
#define MK_ROW       272
#define K2_SMEM      109568

#define LDSM_X4(r, addr) \
    asm volatile("ldmatrix.sync.aligned.m8n8.x4.shared.b16 {%0,%1,%2,%3}, [%4];" \
                 : "=r"((r)[0]), "=r"((r)[1]), "=r"((r)[2]), "=r"((r)[3]) \
                 : "r"(addr))

#define MMA_BF16(acc, a, b0, b1) \
    asm volatile("mma.sync.aligned.m16n8k16.row.col.f32.bf16.bf16.f32 " \
                 "{%0,%1,%2,%3}, {%4,%5,%6,%7}, {%8,%9}, {%0,%1,%2,%3};" \
                 : "+f"((acc)[0]), "+f"((acc)[1]), "+f"((acc)[2]), "+f"((acc)[3]) \
                 : "r"((a)[0]), "r"((a)[1]), "r"((a)[2]), "r"((a)[3]), \
                   "r"(b0), "r"(b1))

__global__ void __launch_bounds__(512, 1)
k2_cfconv_mma(const float* __restrict__ ev,
              const float* __restrict__ mask,
              float* __restrict__ out) {
    extern __shared__ char smc[];
    const uint32_t smem_base = smem_u32(smc);
    const int t    = threadIdx.x;
    const int lane = t & 31;
    const int wid  = t >> 5;
    const int wm   = wid >> 2;     // 0..3: i-subtile of 16
    const int wn   = wid & 3;      // 0..3: d-subtile of 32
    const int b    = blockIdx.x >> 3;
    const int i0   = (blockIdx.x & 7) * 64;

    float acc[3][4][4];
#pragma unroll
    for (int c = 0; c < 3; ++c)
#pragma unroll
        for (int nt = 0; nt < 4; ++nt)
#pragma unroll
            for (int q = 0; q < 4; ++q) acc[c][nt][q] = 0.0f;

    // ldmatrix lane address components
    const uint32_t a_lane = (uint32_t)((wm * 16 + (lane & 15)) * SM_ROW + (lane >> 4) * 16);
    uint32_t b_lane[2];
#pragma unroll
    for (int q = 0; q < 2; ++q) {
        int n = wn * 32 + q * 16 + (lane & 7) + ((lane >> 4) & 1) * 8;
        b_lane[q] = (uint32_t)(B_BASE + n * SM_ROW + ((lane >> 3) & 1) * 16);
    }

    for (int ch = 0; ch < 8; ++ch) {
        const int j0 = ch * 64;
        __syncthreads();   // previous chunk's compute finished

        // ---- mask tile -> smem (64 x 64 f32) and B tiles (hi/lo split of hT)
#pragma unroll
        for (int p = t; p < 1024; p += 512) {
            int i = p >> 4, q = p & 15;
            float4 m4 = ((const float4*)mask)[((size_t)(b * 512 + i0 + i) * 512 + j0) / 4 + q];
            float* dst = (float*)(smc + MK_BASE + i * MK_ROW + q * 16);
            dst[0] = m4.x; dst[1] = m4.y; dst[2] = m4.z; dst[3] = m4.w;
        }
#pragma unroll
        for (int p = t; p < 2048; p += 512) {
            int d = p >> 4, q = p & 15;
            uint4 w = ((const uint4*)g_hT)[((b * 128 + d) * 512 + j0) / 4 + q];
            uint32_t hi0 = __byte_perm(w.x, w.y, 0x5410);
            uint32_t lo0 = __byte_perm(w.x, w.y, 0x7632);
            uint32_t hi1 = __byte_perm(w.z, w.w, 0x5410);
            uint32_t lo1 = __byte_perm(w.z, w.w, 0x7632);
            char* base = smc + B_BASE + d * SM_ROW + q * 8;
            *(uint2*)(base)              = make_uint2(hi0, hi1);
            *(uint2*)(base + B_S_STRIDE) = make_uint2(lo0, lo1);
        }
        __syncthreads();   // mk ready for A conversion

        // ---- A tiles: mev split (truncation hi + rounded lo)
#pragma unroll
        for (int p = t; p < 3072; p += 512) {
            int i   = p / 48;
            int rem = p - i * 48;
            float4 e4 = ((const float4*)ev)[((size_t)(b * 512 + i0 + i) * 512 + j0) * 3 / 4 + rem];
            const float* ep = &e4.x;
#pragma unroll
            for (int q = 0; q < 4; ++q) {
                int l = rem * 4 + q;            // 0..191
                int j = (l * 171) >> 9;         // l / 3
                int c = l - 3 * j;
                float m = *(const float*)(smc + MK_BASE + i * MK_ROW + j * 4);
                float v = ep[q] * m;
                uint32_t vb  = __float_as_uint(v);
                uint32_t hib = vb & 0xFFFF0000u;
                float    lo  = v - __uint_as_float(hib);
                uint16_t lo16 = __bfloat16_as_ushort(__float2bfloat16(lo));
                char* base = smc + c * A_C_STRIDE + i * SM_ROW + j * 2;
                *(uint16_t*)(base)              = (uint16_t)(vb >> 16);
                *(uint16_t*)(base + A_S_STRIDE) = lo16;
            }
        }
        __syncthreads();   // A/B ready

        // ---- compute: 4 k16-steps, 3 passes each
#pragma unroll
        for (int kb = 0; kb < 4; ++kb) {
            uint32_t afr[3][2][4];
            uint32_t bfr[2][2][4];
#pragma unroll
            for (int c = 0; c < 3; ++c)
#pragma unroll
                for (int s = 0; s < 2; ++s)
                    LDSM_X4(afr[c][s],
                            smem_base + c * A_C_STRIDE + s * A_S_STRIDE + a_lane + kb * 32);
#pragma unroll
            for (int s = 0; s < 2; ++s)
#pragma unroll
                for (int q = 0; q < 2; ++q)
                    LDSM_X4(bfr[s][q], smem_base + b_lane[q] + s * B_S_STRIDE + kb * 32);

#pragma unroll
            for (int c = 0; c < 3; ++c) {
#pragma unroll
                for (int nt = 0; nt < 4; ++nt) {
                    uint32_t* bh = bfr[0][nt >> 1];
                    uint32_t* bl = bfr[1][nt >> 1];
                    uint32_t b0h = bh[(nt & 1) * 2], b1h = bh[(nt & 1) * 2 + 1];
                    uint32_t b0l = bl[(nt & 1) * 2], b1l = bl[(nt & 1) * 2 + 1];
                    MMA_BF16(acc[c][nt], afr[c][0], b0h, b1h);   // hi * hi
                    MMA_BF16(acc[c][nt], afr[c][1], b0h, b1h);   // lo * hi
                    MMA_BF16(acc[c][nt], afr[c][0], b0l, b1l);   // hi * lo
                }
            }
        }
    }

    // ---- epilogue: C frags -> out[b][i][c][d], STG.64, 32B-sector efficient
    const int r0 = i0 + wm * 16 + (lane >> 2);
    const int dq = wn * 32 + (lane & 3) * 2;
#pragma unroll
    for (int c = 0; c < 3; ++c) {
#pragma unroll
        for (int nt = 0; nt < 4; ++nt) {
            int d = dq + nt * 8;
            size_t o0 = ((size_t)(b * 512 + r0)     * 3 + c) * 128 + d;
            size_t o1 = ((size_t)(b * 512 + r0 + 8) * 3 + c) * 128 + d;
            *(float2*)(out + o0) = make_float2(acc[c][nt][0], acc[c][nt][1]);
            *(float2*)(out + o1) = make_float2(acc[c][nt][2], acc[c][nt][3]);
        }
    }
}

// ---------------------------------------------------------------------------
extern "C" void kernel_launch(void* const* d_in, const int* in_sizes, int n_in,
                              void* d_out, int out_size) {
    const float* s    = (const float*)d_in[0];   // (32,512,128)
    const float* ev   = (const float*)d_in[1];   // (32,512,512,3)
    const float* mask = (const float*)d_in[2];   // (32,512,512,1)
    const float* W1   = (const float*)d_in[3];   // (128,128)
    const float* b1   = (const float*)d_in[4];   // (128,)
    float* out = (float*)d_out;                  // (32,512,3,128)

    const int k1_smem = (128 * 132 + 128 * 33) * (int)sizeof(float)
                      + 128 * 33 * (int)sizeof(uint32_t);   // 101376
    cudaFuncSetAttribute(k1_lin_ln_silu,
                         cudaFuncAttributeMaxDynamicSharedMemorySize, k1_smem);
    cudaFuncSetAttribute(k2_cfconv_mma,
                         cudaFuncAttributeMaxDynamicSharedMemorySize, K2_SMEM);

    k1_lin_ln_silu<<<(BB * NN) / 32, 256, k1_smem>>>(s, W1, b1);
    k2_cfconv_mma<<<BB * 8, 512, K2_SMEM>>>(ev, mask, out);
}